// round 2
// baseline (speedup 1.0000x reference)
#include <cuda_runtime.h>

#define NNODES 50000
#define NEDGES 100000
#define DIM    768

// Scratch (allocation-free rule: __device__ globals)
__device__ float g_sum[(size_t)NNODES * DIM];   // neighbor-sum / agg buffer
__device__ float g_deg[NNODES];                 // in-degree (same for both layers)
__device__ float g_h[(size_t)NNODES * DIM];     // hidden activations after layer 1

// ---------------------------------------------------------------------------
// Elementwise helpers
// ---------------------------------------------------------------------------
__global__ void zero_f4(float4* __restrict__ p, int n4) {
    int i = blockIdx.x * blockDim.x + threadIdx.x;
    int stride = gridDim.x * blockDim.x;
    float4 z = make_float4(0.f, 0.f, 0.f, 0.f);
    for (; i < n4; i += stride) p[i] = z;
}

__global__ void scatter_deg(const int* __restrict__ ei, float* __restrict__ deg) {
    int e = blockIdx.x * blockDim.x + threadIdx.x;
    if (e < NEDGES) atomicAdd(&deg[ei[NEDGES + e]], 1.0f);
}

// One block per edge: gather src row (coalesced float4), scatter-add to dst row.
__global__ void __launch_bounds__(192) scatter_add(
    const float* __restrict__ feat, const int* __restrict__ ei,
    float* __restrict__ sum)
{
    int e = blockIdx.x;
    int s = ei[e];
    int d = ei[NEDGES + e];
    const float4* xs = (const float4*)(feat + (size_t)s * DIM);
    float*        out = sum + (size_t)d * DIM;
    float4 v = xs[threadIdx.x];
    int i = threadIdx.x * 4;
    atomicAdd(out + i + 0, v.x);
    atomicAdd(out + i + 1, v.y);
    atomicAdd(out + i + 2, v.z);
    atomicAdd(out + i + 3, v.w);
}

__global__ void normalize_k(float4* __restrict__ sum, const float* __restrict__ deg) {
    int i = blockIdx.x * blockDim.x + threadIdx.x;
    int stride = gridDim.x * blockDim.x;
    const int n4 = NNODES * (DIM / 4);
    for (; i < n4; i += stride) {
        int row = i / (DIM / 4);
        float inv = 1.0f / fmaxf(deg[row], 1.0f);
        float4 v = sum[i];
        v.x *= inv; v.y *= inv; v.z *= inv; v.w *= inv;
        sum[i] = v;
    }
}

// ---------------------------------------------------------------------------
// Fused dual-operand SGEMM:
//   out[m, n] = sum_k A1[m,k]*Wl[n,k] + sum_k A2[m,k]*Wr[n,k] + bias[n]
// 128x128 tile, BK=8, 256 threads, 8x8 micro-tile per thread.
// ---------------------------------------------------------------------------
__global__ void __launch_bounds__(256, 2) gemm_dual(
    const float* __restrict__ A1, const float* __restrict__ A2,
    const float* __restrict__ Wl, const float* __restrict__ Wr,
    const float* __restrict__ bias, float* __restrict__ out, int do_relu)
{
    __shared__ float As[8][128];
    __shared__ float Bs[8][128];

    const int m0 = blockIdx.x * 128;
    const int n0 = blockIdx.y * 128;
    const int t  = threadIdx.x;
    const int tx = t & 15;        // 0..15 -> n micro-tile
    const int ty = t >> 4;        // 0..15 -> m micro-tile
    const int lrow = t >> 1;      // 0..127 load row
    const int lcol = (t & 1) << 2;// 0 or 4 load col group

    float acc[8][8];
#pragma unroll
    for (int i = 0; i < 8; i++)
#pragma unroll
        for (int j = 0; j < 8; j++) acc[i][j] = 0.f;

    const int  arow   = m0 + lrow;
    const bool avalid = (arow < NNODES);

#pragma unroll 1
    for (int pair = 0; pair < 2; ++pair) {
        const float* A = pair ? A2 : A1;
        const float* W = pair ? Wr : Wl;
        const float* aptr = A + (size_t)arow * DIM + lcol;
        const float* wptr = W + (size_t)(n0 + lrow) * DIM + lcol;

#pragma unroll 1
        for (int k0 = 0; k0 < DIM; k0 += 8) {
            float4 av = avalid ? *(const float4*)(aptr + k0)
                               : make_float4(0.f, 0.f, 0.f, 0.f);
            float4 bv = *(const float4*)(wptr + k0);
            As[lcol + 0][lrow] = av.x;
            As[lcol + 1][lrow] = av.y;
            As[lcol + 2][lrow] = av.z;
            As[lcol + 3][lrow] = av.w;
            Bs[lcol + 0][lrow] = bv.x;
            Bs[lcol + 1][lrow] = bv.y;
            Bs[lcol + 2][lrow] = bv.z;
            Bs[lcol + 3][lrow] = bv.w;
            __syncthreads();

#pragma unroll
            for (int k = 0; k < 8; ++k) {
                float a[8], b[8];
#pragma unroll
                for (int i = 0; i < 8; i++) a[i] = As[k][ty * 8 + i];
#pragma unroll
                for (int j = 0; j < 8; j++) b[j] = Bs[k][tx * 8 + j];
#pragma unroll
                for (int i = 0; i < 8; i++)
#pragma unroll
                    for (int j = 0; j < 8; j++) acc[i][j] += a[i] * b[j];
            }
            __syncthreads();
        }
    }

    // Epilogue: bias (+relu), vectorized store
#pragma unroll
    for (int i = 0; i < 8; i++) {
        int row = m0 + ty * 8 + i;
        if (row < NNODES) {
#pragma unroll
            for (int j = 0; j < 8; j += 4) {
                int col = n0 + tx * 8 + j;
                float4 v;
                v.x = acc[i][j + 0] + bias[col + 0];
                v.y = acc[i][j + 1] + bias[col + 1];
                v.z = acc[i][j + 2] + bias[col + 2];
                v.w = acc[i][j + 3] + bias[col + 3];
                if (do_relu) {
                    v.x = fmaxf(v.x, 0.f); v.y = fmaxf(v.y, 0.f);
                    v.z = fmaxf(v.z, 0.f); v.w = fmaxf(v.w, 0.f);
                }
                *(float4*)(out + (size_t)row * DIM + col) = v;
            }
        }
    }
}

// ---------------------------------------------------------------------------
extern "C" void kernel_launch(void* const* d_in, const int* in_sizes, int n_in,
                              void* d_out, int out_size)
{
    const float* x   = (const float*)d_in[0];
    const int*   ei  = (const int*)d_in[1];     // int32! (JAX x64 disabled)
    const float* W1l = (const float*)d_in[2];
    const float* b1l = (const float*)d_in[3];
    const float* W1r = (const float*)d_in[4];
    const float* W2l = (const float*)d_in[5];
    const float* b2l = (const float*)d_in[6];
    const float* W2r = (const float*)d_in[7];
    float*       out = (float*)d_out;

    float *sum, *deg, *h;
    cudaGetSymbolAddress((void**)&sum, g_sum);
    cudaGetSymbolAddress((void**)&deg, g_deg);
    cudaGetSymbolAddress((void**)&h,   g_h);

    const int n4 = NNODES * (DIM / 4);
    dim3 gemm_grid((NNODES + 127) / 128, DIM / 128);

    // ---- Layer 1 ----
    zero_f4<<<2048, 256>>>((float4*)sum, n4);
    zero_f4<<<64, 256>>>((float4*)deg, NNODES / 4);
    scatter_deg<<<(NEDGES + 255) / 256, 256>>>(ei, deg);
    scatter_add<<<NEDGES, 192>>>(x, ei, sum);
    normalize_k<<<2048, 256>>>((float4*)sum, deg);
    gemm_dual<<<gemm_grid, 256>>>(sum, x, W1l, W1r, b1l, h, 1);

    // ---- Layer 2 (degree unchanged) ----
    zero_f4<<<2048, 256>>>((float4*)sum, n4);
    scatter_add<<<NEDGES, 192>>>(h, ei, sum);
    normalize_k<<<2048, 256>>>((float4*)sum, deg);
    gemm_dual<<<gemm_grid, 256>>>(sum, h, W2l, W2r, b2l, out, 0);
}

// round 4
// speedup vs baseline: 2.5812x; 2.5812x over previous
#include <cuda_runtime.h>
#include <cuda_bf16.h>
#include <cstdint>

#define NNODES    50000
#define NROWS_PAD 50048
#define NEDGES    100000
#define DIM       768
#define KCAT      3072      // [A1hi | A1lo | A2hi | A2lo] x 768

// ---- scratch (allocation-free rule: __device__ globals) -------------------
__device__ float g_sum[(size_t)NNODES * DIM];
__device__ float g_deg[NNODES];
__device__ float g_h[(size_t)NNODES * DIM];
__device__ __nv_bfloat16 g_acat[(size_t)NROWS_PAD * KCAT];  // 307 MB
__device__ __nv_bfloat16 g_wcat[(size_t)DIM * KCAT];        // 4.7 MB

// 6 K-segments = {pair0: hi@hi, lo@hi, hi@lo, pair1: hi@hi, lo@hi, hi@lo}
__constant__ int c_seg_a[6] = {0, 768, 0,   1536, 2304, 1536};
__constant__ int c_seg_w[6] = {0, 0,   768, 1536, 1536, 2304};

// ---------------------------------------------------------------------------
__device__ __forceinline__ uint32_t smem_u32(const void* p) {
    uint32_t a;
    asm("{ .reg .u64 t; cvta.to.shared.u64 t, %1; cvt.u32.u64 %0, t; }"
        : "=r"(a) : "l"(p));
    return a;
}

// ---------------------------------------------------------------------------
// Aggregation kernels (from passing baseline)
// ---------------------------------------------------------------------------
__global__ void zero_f4(float4* __restrict__ p, int n4) {
    int i = blockIdx.x * blockDim.x + threadIdx.x;
    int stride = gridDim.x * blockDim.x;
    float4 z = make_float4(0.f, 0.f, 0.f, 0.f);
    for (; i < n4; i += stride) p[i] = z;
}
__global__ void scatter_deg(const int* __restrict__ ei, float* __restrict__ deg) {
    int e = blockIdx.x * blockDim.x + threadIdx.x;
    if (e < NEDGES) atomicAdd(&deg[ei[NEDGES + e]], 1.0f);
}
__global__ void __launch_bounds__(192) scatter_add(
    const float* __restrict__ feat, const int* __restrict__ ei,
    float* __restrict__ sum)
{
    int e = blockIdx.x;
    int s = ei[e];
    int d = ei[NEDGES + e];
    const float4* xs = (const float4*)(feat + (size_t)s * DIM);
    float* out = sum + (size_t)d * DIM;
    float4 v = xs[threadIdx.x];
    int i = threadIdx.x * 4;
    atomicAdd(out + i + 0, v.x);
    atomicAdd(out + i + 1, v.y);
    atomicAdd(out + i + 2, v.z);
    atomicAdd(out + i + 3, v.w);
}

// ---------------------------------------------------------------------------
// fp32 -> (bf16 hi, bf16 lo) split conversions
// ---------------------------------------------------------------------------
__device__ __forceinline__ void split4(float4 v, __nv_bfloat16* hi, __nv_bfloat16* lo) {
    __nv_bfloat16 h0 = __float2bfloat16(v.x), h1 = __float2bfloat16(v.y);
    __nv_bfloat16 h2 = __float2bfloat16(v.z), h3 = __float2bfloat16(v.w);
    float l0 = v.x - __bfloat162float(h0), l1 = v.y - __bfloat162float(h1);
    float l2 = v.z - __bfloat162float(h2), l3 = v.w - __bfloat162float(h3);
    ((__nv_bfloat162*)hi)[0] = __nv_bfloat162(h0, h1);
    ((__nv_bfloat162*)hi)[1] = __nv_bfloat162(h2, h3);
    ((__nv_bfloat162*)lo)[0] = __nv_bfloat162(__float2bfloat16(l0), __float2bfloat16(l1));
    ((__nv_bfloat162*)lo)[1] = __nv_bfloat162(__float2bfloat16(l2), __float2bfloat16(l3));
}

__global__ void convert_a(const float4* __restrict__ sum, const float* __restrict__ deg,
                          const float4* __restrict__ x2, __nv_bfloat16* __restrict__ acat)
{
    const int F4 = DIM / 4;
    int i = blockIdx.x * blockDim.x + threadIdx.x;
    if (i >= NROWS_PAD * F4) return;
    int r = i / F4, c = (i % F4) * 4;
    float4 v1 = make_float4(0.f, 0.f, 0.f, 0.f), v2 = v1;
    if (r < NNODES) {
        float inv = 1.0f / fmaxf(deg[r], 1.0f);
        v1 = sum[i];
        v1.x *= inv; v1.y *= inv; v1.z *= inv; v1.w *= inv;
        v2 = x2[i];
    }
    __nv_bfloat16* row = acat + (size_t)r * KCAT;
    split4(v1, row + c,        row + 768 + c);
    split4(v2, row + 1536 + c, row + 2304 + c);
}

__global__ void convert_w(const float4* __restrict__ Wl, const float4* __restrict__ Wr,
                          __nv_bfloat16* __restrict__ wcat)
{
    const int F4 = DIM / 4;
    int i = blockIdx.x * blockDim.x + threadIdx.x;
    if (i >= DIM * F4) return;
    int r = i / F4, c = (i % F4) * 4;
    __nv_bfloat16* row = wcat + (size_t)r * KCAT;
    split4(Wl[i], row + c,        row + 768 + c);
    split4(Wr[i], row + 1536 + c, row + 2304 + c);
}

// ---------------------------------------------------------------------------
// bf16 mma.sync GEMM: out[128m x 128n] = Acat @ Wcat^T (eff. K=4608) + bias
// BM=BN=128, BK=64, 3-stage cp.async, 8 warps (2m x 4n), warp tile 64x32.
// smem rows are 128B (64 bf16), 16B-chunk XOR swizzle: chunk' = chunk ^ (row&7)
// ---------------------------------------------------------------------------
#define BK       64
#define ROW_B    128                 // bytes per smem row
#define TILE_B   (128 * ROW_B)       // 16 KB
#define STAGE_B  (2 * TILE_B)        // A + B per stage
#define NSTAGE   3
#define SMEM_GEMM (NSTAGE * STAGE_B) // 96 KB
#define NCHUNK   72                  // 6 segments x 12 chunks of 64

__device__ __forceinline__ void cp_async16(uint32_t saddr, const void* gaddr) {
    asm volatile("cp.async.cg.shared.global [%0], [%1], 16;"
                 :: "r"(saddr), "l"(gaddr));
}
__device__ __forceinline__ void cp_commit() {
    asm volatile("cp.async.commit_group;" ::: "memory");
}
__device__ __forceinline__ void cp_wait2() {
    asm volatile("cp.async.wait_group 2;" ::: "memory");
}
__device__ __forceinline__ void ldmatrix4(uint32_t* a, uint32_t addr) {
    asm volatile("ldmatrix.sync.aligned.m8n8.x4.shared.b16 {%0,%1,%2,%3}, [%4];"
                 : "=r"(a[0]), "=r"(a[1]), "=r"(a[2]), "=r"(a[3]) : "r"(addr));
}
__device__ __forceinline__ void mma_bf16(float* c, const uint32_t* a, const uint32_t* b) {
    asm volatile(
        "mma.sync.aligned.m16n8k16.row.col.f32.bf16.bf16.f32 "
        "{%0,%1,%2,%3}, {%4,%5,%6,%7}, {%8,%9}, {%0,%1,%2,%3};"
        : "+f"(c[0]), "+f"(c[1]), "+f"(c[2]), "+f"(c[3])
        : "r"(a[0]), "r"(a[1]), "r"(a[2]), "r"(a[3]), "r"(b[0]), "r"(b[1]));
}

__device__ __forceinline__ void load_stage(
    uint32_t s_stage, const char* Ab, const char* Bb,
    size_t goffA, size_t goffB, int tid)
{
    const int j  = tid & 7;        // 16B chunk in row
    const int r0 = tid >> 3;       // 32 rows per pass
#pragma unroll
    for (int s = 0; s < 4; ++s) {
        int row = r0 + s * 32;
        uint32_t soff = row * ROW_B + ((j ^ (row & 7)) << 4);
        const char* ga = Ab + (size_t)row * (KCAT * 2) + goffA + j * 16;
        const char* gb = Bb + (size_t)row * (KCAT * 2) + goffB + j * 16;
        cp_async16(s_stage + soff, ga);
        cp_async16(s_stage + TILE_B + soff, gb);
    }
}

__global__ void __launch_bounds__(256) gemm_mma(
    const __nv_bfloat16* __restrict__ acat, const __nv_bfloat16* __restrict__ wcat,
    const float* __restrict__ bias, float* __restrict__ out, int do_relu)
{
    extern __shared__ char smem[];
    const uint32_t sb = smem_u32(smem);
    const int tid = threadIdx.x;
    const int wid = tid >> 5, lid = tid & 31;
    const int wm = (wid & 1) * 64;        // warp m offset (2 rows of warps)
    const int wn = (wid >> 1) * 32;       // warp n offset (4 cols of warps)
    const int n0 = blockIdx.x * 128;      // n-major grid: A reuse across 6 x-blocks
    const int m0 = blockIdx.y * 128;

    const char* Ab = (const char*)acat + (size_t)m0 * (KCAT * 2);
    const char* Bb = (const char*)wcat + (size_t)n0 * (KCAT * 2);

    float acc[4][4][4];
#pragma unroll
    for (int i = 0; i < 4; i++)
#pragma unroll
        for (int j = 0; j < 4; j++)
#pragma unroll
            for (int k = 0; k < 4; k++) acc[i][j][k] = 0.f;

    // prologue: stages 0..2
#pragma unroll
    for (int p = 0; p < NSTAGE; ++p) {
        const int seg = p / 12, kc = p % 12;
        load_stage(sb + p * STAGE_B, Ab, Bb,
                   (size_t)c_seg_a[seg] * 2 + (size_t)kc * 128,
                   (size_t)c_seg_w[seg] * 2 + (size_t)kc * 128, tid);
        cp_commit();
    }

    // precomputed fragment addresses (stage-relative)
    const int arow = (lid & 15);                  // + wm + mt*16
    const int achunk_sel = (lid >> 4);            // 0/1 -> k half
    const int bn_lane = (lid >> 2);               // + wn + nt*8
    const int bk_off = (lid & 3) * 4;             // byte offset in 16B chunk

    int stage = 0;
    for (int c = 0; c < NCHUNK; ++c) {
        cp_wait2();
        __syncthreads();

        const uint32_t sA = sb + stage * STAGE_B;
        const uint32_t sB = sA + TILE_B;

#pragma unroll
        for (int ks = 0; ks < 4; ++ks) {
            uint32_t bfrag[4][2];
#pragma unroll
            for (int nt = 0; nt < 4; ++nt) {
                int n = wn + nt * 8 + bn_lane;
                uint32_t base = sB + n * ROW_B + bk_off;
                uint32_t a0 = base + ((((ks * 2) ^ (n & 7))) << 4);
                uint32_t a1 = base + ((((ks * 2 + 1) ^ (n & 7))) << 4);
                asm volatile("ld.shared.b32 %0, [%1];" : "=r"(bfrag[nt][0]) : "r"(a0));
                asm volatile("ld.shared.b32 %0, [%1];" : "=r"(bfrag[nt][1]) : "r"(a1));
            }
#pragma unroll
            for (int mt = 0; mt < 4; ++mt) {
                int row = wm + mt * 16 + arow;
                uint32_t aaddr = sA + row * ROW_B +
                                 (((ks * 2 + achunk_sel) ^ (row & 7)) << 4);
                uint32_t afrag[4];
                ldmatrix4(afrag, aaddr);
#pragma unroll
                for (int nt = 0; nt < 4; ++nt)
                    mma_bf16(acc[mt][nt], afrag, bfrag[nt]);
            }
        }
        __syncthreads();   // all warps done reading before refill

        const int cn = c + NSTAGE;
        if (cn < NCHUNK) {
            const int seg = cn / 12, kc = cn % 12;
            load_stage(sb + stage * STAGE_B, Ab, Bb,
                       (size_t)c_seg_a[seg] * 2 + (size_t)kc * 128,
                       (size_t)c_seg_w[seg] * 2 + (size_t)kc * 128, tid);
        }
        cp_commit();
        stage = (stage + 1 == NSTAGE) ? 0 : stage + 1;
    }

    // epilogue: bias (+relu), float2 stores
    float bfr[4][2];
#pragma unroll
    for (int nt = 0; nt < 4; ++nt) {
        int col = n0 + wn + nt * 8 + (lid & 3) * 2;
        bfr[nt][0] = bias[col + 0];
        bfr[nt][1] = bias[col + 1];
    }
#pragma unroll
    for (int mt = 0; mt < 4; ++mt) {
        int row_lo = m0 + wm + mt * 16 + (lid >> 2);
#pragma unroll
        for (int h = 0; h < 2; ++h) {
            int row = row_lo + h * 8;
            if (row < NNODES) {
                float* orow = out + (size_t)row * DIM;
#pragma unroll
                for (int nt = 0; nt < 4; ++nt) {
                    int col = n0 + wn + nt * 8 + (lid & 3) * 2;
                    float2 v;
                    v.x = acc[mt][nt][h * 2 + 0] + bfr[nt][0];
                    v.y = acc[mt][nt][h * 2 + 1] + bfr[nt][1];
                    if (do_relu) { v.x = fmaxf(v.x, 0.f); v.y = fmaxf(v.y, 0.f); }
                    *(float2*)(orow + col) = v;
                }
            }
        }
    }
}

// ---------------------------------------------------------------------------
extern "C" void kernel_launch(void* const* d_in, const int* in_sizes, int n_in,
                              void* d_out, int out_size)
{
    const float* x   = (const float*)d_in[0];
    const int*   ei  = (const int*)d_in[1];     // int32 (JAX x64 disabled)
    const float* W1l = (const float*)d_in[2];
    const float* b1l = (const float*)d_in[3];
    const float* W1r = (const float*)d_in[4];
    const float* W2l = (const float*)d_in[5];
    const float* b2l = (const float*)d_in[6];
    const float* W2r = (const float*)d_in[7];
    float*       out = (float*)d_out;

    float *sum, *deg, *h;
    __nv_bfloat16 *acat, *wcat;
    cudaGetSymbolAddress((void**)&sum,  g_sum);
    cudaGetSymbolAddress((void**)&deg,  g_deg);
    cudaGetSymbolAddress((void**)&h,    g_h);
    cudaGetSymbolAddress((void**)&acat, g_acat);
    cudaGetSymbolAddress((void**)&wcat, g_wcat);

    cudaFuncSetAttribute(gemm_mma, cudaFuncAttributeMaxDynamicSharedMemorySize,
                         SMEM_GEMM);

    const int n4 = NNODES * (DIM / 4);
    const int convA_blocks = (NROWS_PAD * (DIM / 4) + 255) / 256;
    const int convW_blocks = (DIM * (DIM / 4) + 255) / 256;
    dim3 gg(DIM / 128, NROWS_PAD / 128);   // (6, 391): n-major for A reuse

    // ---- Layer 1 ----
    zero_f4<<<2048, 256>>>((float4*)sum, n4);
    zero_f4<<<64, 256>>>((float4*)deg, NNODES / 4);
    scatter_deg<<<(NEDGES + 255) / 256, 256>>>(ei, deg);
    scatter_add<<<NEDGES, 192>>>(x, ei, sum);
    convert_w<<<convW_blocks, 256>>>((const float4*)W1l, (const float4*)W1r, wcat);
    convert_a<<<convA_blocks, 256>>>((const float4*)sum, deg, (const float4*)x, acat);
    gemm_mma<<<gg, 256, SMEM_GEMM>>>(acat, wcat, b1l, h, 1);

    // ---- Layer 2 (degree unchanged) ----
    zero_f4<<<2048, 256>>>((float4*)sum, n4);
    scatter_add<<<NEDGES, 192>>>(h, ei, sum);
    convert_w<<<convW_blocks, 256>>>((const float4*)W2l, (const float4*)W2r, wcat);
    convert_a<<<convA_blocks, 256>>>((const float4*)sum, deg, (const float4*)h, acat);
    gemm_mma<<<gg, 256, SMEM_GEMM>>>(acat, wcat, b2l, out, 0);
}

// round 5
// speedup vs baseline: 2.6165x; 1.0137x over previous
#include <cuda_runtime.h>
#include <cuda_bf16.h>
#include <cstdint>

#define NNODES    50000
#define NROWS_PAD 50048
#define NEDGES    100000
#define DIM       768
#define KSTOR     1536       // A row: [hi(768) | lo(768)]
#define NOUT      1536       // T cols: [x@Wl^T (768) | x@Wr^T (768)]

// ---- scratch (allocation-free rule: __device__ globals) -------------------
__device__ float g_sum[(size_t)NNODES * DIM];               // 153 MB
__device__ float g_deg[NNODES];
__device__ float g_T[(size_t)NROWS_PAD * NOUT];             // 307 MB
__device__ __nv_bfloat16 g_acat[(size_t)NROWS_PAD * KSTOR]; // 154 MB
__device__ __nv_bfloat16 g_wcat[(size_t)NOUT * KSTOR];      // 4.7 MB

// 3 eff-K segments: hi@hi, lo@hi, hi@lo  (byte offsets applied below)
__constant__ int c_seg_a[3] = {0, 768, 0};
__constant__ int c_seg_w[3] = {0, 0, 768};

// ---------------------------------------------------------------------------
__device__ __forceinline__ uint32_t smem_u32(const void* p) {
    uint32_t a;
    asm("{ .reg .u64 t; cvta.to.shared.u64 t, %1; cvt.u32.u64 %0, t; }"
        : "=r"(a) : "l"(p));
    return a;
}

// ---------------------------------------------------------------------------
// Aggregation kernels
// ---------------------------------------------------------------------------
__global__ void zero_f4(float4* __restrict__ p, int n4) {
    int i = blockIdx.x * blockDim.x + threadIdx.x;
    int stride = gridDim.x * blockDim.x;
    float4 z = make_float4(0.f, 0.f, 0.f, 0.f);
    for (; i < n4; i += stride) p[i] = z;
}
__global__ void scatter_deg(const int* __restrict__ ei, float* __restrict__ deg) {
    int e = blockIdx.x * blockDim.x + threadIdx.x;
    if (e < NEDGES) atomicAdd(&deg[ei[NEDGES + e]], 1.0f);
}
// gather src row of T's left half (row stride NOUT), scatter-add into sum
__global__ void __launch_bounds__(192) scatter_addT(
    const float* __restrict__ T, const int* __restrict__ ei,
    float* __restrict__ sum)
{
    int e = blockIdx.x;
    int s = ei[e];
    int d = ei[NEDGES + e];
    const float4* xs = (const float4*)(T + (size_t)s * NOUT);
    float* out = sum + (size_t)d * DIM;
    float4 v = xs[threadIdx.x];
    int i = threadIdx.x * 4;
    atomicAdd(out + i + 0, v.x);
    atomicAdd(out + i + 1, v.y);
    atomicAdd(out + i + 2, v.z);
    atomicAdd(out + i + 3, v.w);
}

// ---------------------------------------------------------------------------
// fp32 -> (bf16 hi, bf16 lo) split helpers
// ---------------------------------------------------------------------------
__device__ __forceinline__ void split4(float4 v, __nv_bfloat16* hi, __nv_bfloat16* lo) {
    __nv_bfloat16 h0 = __float2bfloat16(v.x), h1 = __float2bfloat16(v.y);
    __nv_bfloat16 h2 = __float2bfloat16(v.z), h3 = __float2bfloat16(v.w);
    float l0 = v.x - __bfloat162float(h0), l1 = v.y - __bfloat162float(h1);
    float l2 = v.z - __bfloat162float(h2), l3 = v.w - __bfloat162float(h3);
    ((__nv_bfloat162*)hi)[0] = __nv_bfloat162(h0, h1);
    ((__nv_bfloat162*)hi)[1] = __nv_bfloat162(h2, h3);
    ((__nv_bfloat162*)lo)[0] = __nv_bfloat162(__float2bfloat16(l0), __float2bfloat16(l1));
    ((__nv_bfloat162*)lo)[1] = __nv_bfloat162(__float2bfloat16(l2), __float2bfloat16(l3));
}

// x fp32 -> acat [hi|lo], zero padding rows
__global__ void convert_x(const float4* __restrict__ x, __nv_bfloat16* __restrict__ acat) {
    const int F4 = DIM / 4;
    int i = blockIdx.x * blockDim.x + threadIdx.x;
    if (i >= NROWS_PAD * F4) return;
    int r = i / F4, c = (i % F4) * 4;
    float4 v = (r < NNODES) ? x[i] : make_float4(0.f, 0.f, 0.f, 0.f);
    __nv_bfloat16* row = acat + (size_t)r * KSTOR;
    split4(v, row + c, row + DIM + c);
}

// build Wcat: rows 0..767 = Wl (hi|lo), rows 768..1535 = Wr (hi|lo)
__global__ void convert_w(const float4* __restrict__ Wl, const float4* __restrict__ Wr,
                          __nv_bfloat16* __restrict__ wcat)
{
    const int F4 = DIM / 4;
    int i = blockIdx.x * blockDim.x + threadIdx.x;
    if (i >= NOUT * F4) return;
    int r = i / F4, c = (i % F4) * 4;
    float4 v = (r < DIM) ? Wl[i] : Wr[i - DIM * F4];
    __nv_bfloat16* row = wcat + (size_t)r * KSTOR;
    split4(v, row + c, row + DIM + c);
}

// layer-1 combine: h = relu(sum/deg + b + T_r); write bf16 split into acat
__global__ void combine_split(const float4* __restrict__ sum, const float* __restrict__ deg,
                              const float* __restrict__ bias, const float* __restrict__ T,
                              __nv_bfloat16* __restrict__ acat)
{
    const int F4 = DIM / 4;
    int i = blockIdx.x * blockDim.x + threadIdx.x;
    if (i >= NROWS_PAD * F4) return;
    int r = i / F4, c = (i % F4) * 4;
    float4 v = make_float4(0.f, 0.f, 0.f, 0.f);
    if (r < NNODES) {
        float inv = 1.0f / fmaxf(deg[r], 1.0f);
        float4 s = sum[i];
        const float4* tr = (const float4*)(T + (size_t)r * NOUT + DIM + c);
        float4 t = *tr;
        v.x = fmaxf(s.x * inv + bias[c + 0] + t.x, 0.f);
        v.y = fmaxf(s.y * inv + bias[c + 1] + t.y, 0.f);
        v.z = fmaxf(s.z * inv + bias[c + 2] + t.z, 0.f);
        v.w = fmaxf(s.w * inv + bias[c + 3] + t.w, 0.f);
    }
    __nv_bfloat16* row = acat + (size_t)r * KSTOR;
    split4(v, row + c, row + DIM + c);
}

// layer-2 combine: out = sum/deg + b + T_r
__global__ void combine_final(const float4* __restrict__ sum, const float* __restrict__ deg,
                              const float* __restrict__ bias, const float* __restrict__ T,
                              float4* __restrict__ out)
{
    const int F4 = DIM / 4;
    int i = blockIdx.x * blockDim.x + threadIdx.x;
    if (i >= NNODES * F4) return;
    int r = i / F4, c = (i % F4) * 4;
    float inv = 1.0f / fmaxf(deg[r], 1.0f);
    float4 s = sum[i];
    float4 t = *(const float4*)(T + (size_t)r * NOUT + DIM + c);
    float4 v;
    v.x = s.x * inv + bias[c + 0] + t.x;
    v.y = s.y * inv + bias[c + 1] + t.y;
    v.z = s.z * inv + bias[c + 2] + t.z;
    v.w = s.w * inv + bias[c + 3] + t.w;
    out[i] = v;
}

// ---------------------------------------------------------------------------
// bf16 mma.sync GEMM v2: T[128m x 256n] = acat @ wcat^T (eff K=2304)
// BM=128 BN=256 BK=64, 8 warps (2m x 4n), warp tile 64x64,
// 4-slot cp.async pipeline, 1 syncthreads/iter, ldmatrix for A and B.
// ---------------------------------------------------------------------------
#define BM 128
#define BN 256
#define ROW_B 128                   // bytes per smem row (64 bf16)
#define ATILE_B (BM * ROW_B)        // 16 KB
#define BTILE_B (BN * ROW_B)        // 32 KB
#define STG_B   (ATILE_B + BTILE_B) // 48 KB
#define NSLOT 4
#define SMEM_GEMM (NSLOT * STG_B)   // 192 KB
#define NCH 36                      // 3 segs x 12 chunks of 64

__device__ __forceinline__ void cp_async16(uint32_t saddr, const void* gaddr) {
    asm volatile("cp.async.cg.shared.global [%0], [%1], 16;"
                 :: "r"(saddr), "l"(gaddr));
}
__device__ __forceinline__ void cp_commit() {
    asm volatile("cp.async.commit_group;" ::: "memory");
}
__device__ __forceinline__ void cp_wait2() {
    asm volatile("cp.async.wait_group 2;" ::: "memory");
}
__device__ __forceinline__ void ldmatrix4(uint32_t* a, uint32_t addr) {
    asm volatile("ldmatrix.sync.aligned.m8n8.x4.shared.b16 {%0,%1,%2,%3}, [%4];"
                 : "=r"(a[0]), "=r"(a[1]), "=r"(a[2]), "=r"(a[3]) : "r"(addr));
}
__device__ __forceinline__ void mma_bf16(float* c, const uint32_t* a, const uint32_t* b) {
    asm volatile(
        "mma.sync.aligned.m16n8k16.row.col.f32.bf16.bf16.f32 "
        "{%0,%1,%2,%3}, {%4,%5,%6,%7}, {%8,%9}, {%0,%1,%2,%3};"
        : "+f"(c[0]), "+f"(c[1]), "+f"(c[2]), "+f"(c[3])
        : "r"(a[0]), "r"(a[1]), "r"(a[2]), "r"(a[3]), "r"(b[0]), "r"(b[1]));
}

__device__ __forceinline__ void load_stage(
    uint32_t slot_base, const char* Ab, const char* Bb,
    size_t goffA, size_t goffB, int tid)
{
    const int j  = tid & 7;        // 16B chunk in 128B row
    const int r0 = tid >> 3;       // 0..31
    const size_t gj = (size_t)j * 16;
#pragma unroll
    for (int s = 0; s < 4; ++s) {
        int row = r0 + s * 32;
        uint32_t soff = row * ROW_B + ((j ^ (row & 7)) << 4);
        cp_async16(slot_base + soff,
                   Ab + (size_t)row * (KSTOR * 2) + goffA + gj);
    }
#pragma unroll
    for (int s = 0; s < 8; ++s) {
        int row = r0 + s * 32;
        uint32_t soff = row * ROW_B + ((j ^ (row & 7)) << 4);
        cp_async16(slot_base + ATILE_B + soff,
                   Bb + (size_t)row * (KSTOR * 2) + goffB + gj);
    }
}

__global__ void __launch_bounds__(256, 1) gemm_mma2(
    const __nv_bfloat16* __restrict__ acat, const __nv_bfloat16* __restrict__ wcat,
    float* __restrict__ T)
{
    extern __shared__ char smem[];
    const uint32_t sb = smem_u32(smem);
    const int tid = threadIdx.x;
    const int wid = tid >> 5, lid = tid & 31;
    const int wm = (wid & 1) * 64;
    const int wn = (wid >> 1) * 64;
    const int n0 = blockIdx.x * BN;       // x fastest: 6 CTAs reuse same A tile
    const int m0 = blockIdx.y * BM;

    const char* Ab = (const char*)acat + (size_t)m0 * (KSTOR * 2);
    const char* Bb = (const char*)wcat + (size_t)n0 * (KSTOR * 2);

    float acc[4][8][4];
#pragma unroll
    for (int i = 0; i < 4; i++)
#pragma unroll
        for (int j = 0; j < 8; j++)
#pragma unroll
            for (int k = 0; k < 4; k++) acc[i][j][k] = 0.f;

    // prologue: stages 0..2 into slots 0..2
#pragma unroll
    for (int p = 0; p < 3; ++p) {
        const int seg = p / 12, kc = p % 12;
        load_stage(sb + p * STG_B, Ab, Bb,
                   (size_t)c_seg_a[seg] * 2 + (size_t)kc * 128,
                   (size_t)c_seg_w[seg] * 2 + (size_t)kc * 128, tid);
        cp_commit();
    }

    // lane-constant addressing pieces
    const uint32_t swz = lid & 7;
    const uint32_t cA = lid >> 4;            // A k-chunk bit
    const uint32_t cB = (lid >> 3) & 1;      // B k-chunk bit
    uint32_t rowoffA[4], rowoffB[4];
#pragma unroll
    for (int mt = 0; mt < 4; ++mt)
        rowoffA[mt] = (wm + mt * 16 + (lid & 15)) * ROW_B;
#pragma unroll
    for (int nt = 0; nt < 4; ++nt)
        rowoffB[nt] = ATILE_B + (wn + nt * 16 + ((lid >> 4) * 8 + (lid & 7))) * ROW_B;

    for (int c = 0; c < NCH; ++c) {
        cp_wait2();
        __syncthreads();   // stage c visible; slot (c+3)&3 fully drained (iter c-1)

        const int cn = c + 3;
        if (cn < NCH) {
            const int seg = cn / 12, kc = cn % 12;
            load_stage(sb + (cn & 3) * STG_B, Ab, Bb,
                       (size_t)c_seg_a[seg] * 2 + (size_t)kc * 128,
                       (size_t)c_seg_w[seg] * 2 + (size_t)kc * 128, tid);
        }
        cp_commit();

        const uint32_t sS = sb + (c & 3) * STG_B;
#pragma unroll
        for (int ks = 0; ks < 4; ++ks) {
            uint32_t bfrag[8][2];
#pragma unroll
            for (int nt = 0; nt < 4; ++nt) {
                uint32_t r[4];
                ldmatrix4(r, sS + rowoffB[nt] + (((ks * 2 + cB) ^ swz) << 4));
                bfrag[nt * 2 + 0][0] = r[0]; bfrag[nt * 2 + 0][1] = r[1];
                bfrag[nt * 2 + 1][0] = r[2]; bfrag[nt * 2 + 1][1] = r[3];
            }
#pragma unroll
            for (int mt = 0; mt < 4; ++mt) {
                uint32_t afrag[4];
                ldmatrix4(afrag, sS + rowoffA[mt] + (((ks * 2 + cA) ^ swz) << 4));
#pragma unroll
                for (int nt = 0; nt < 8; ++nt)
                    mma_bf16(acc[mt][nt], afrag, bfrag[nt]);
            }
        }
    }

    // epilogue: raw fp32 store to T (bias/relu handled downstream)
#pragma unroll
    for (int mt = 0; mt < 4; ++mt) {
        int row_lo = m0 + wm + mt * 16 + (lid >> 2);
#pragma unroll
        for (int h = 0; h < 2; ++h) {
            int row = row_lo + h * 8;
            float* orow = T + (size_t)row * NOUT;
#pragma unroll
            for (int nt = 0; nt < 8; ++nt) {
                int col = n0 + wn + nt * 8 + (lid & 3) * 2;
                float2 v;
                v.x = acc[mt][nt][h * 2 + 0];
                v.y = acc[mt][nt][h * 2 + 1];
                *(float2*)(orow + col) = v;
            }
        }
    }
}

// ---------------------------------------------------------------------------
extern "C" void kernel_launch(void* const* d_in, const int* in_sizes, int n_in,
                              void* d_out, int out_size)
{
    const float* x   = (const float*)d_in[0];
    const int*   ei  = (const int*)d_in[1];     // int32 (JAX x64 disabled)
    const float* W1l = (const float*)d_in[2];
    const float* b1l = (const float*)d_in[3];
    const float* W1r = (const float*)d_in[4];
    const float* W2l = (const float*)d_in[5];
    const float* b2l = (const float*)d_in[6];
    const float* W2r = (const float*)d_in[7];
    float*       out = (float*)d_out;

    float *sum, *deg, *T;
    __nv_bfloat16 *acat, *wcat;
    cudaGetSymbolAddress((void**)&sum,  g_sum);
    cudaGetSymbolAddress((void**)&deg,  g_deg);
    cudaGetSymbolAddress((void**)&T,    g_T);
    cudaGetSymbolAddress((void**)&acat, g_acat);
    cudaGetSymbolAddress((void**)&wcat, g_wcat);

    cudaFuncSetAttribute(gemm_mma2, cudaFuncAttributeMaxDynamicSharedMemorySize,
                         SMEM_GEMM);

    const int n4 = NNODES * (DIM / 4);
    const int rows_blocks = (NROWS_PAD * (DIM / 4) + 255) / 256;
    const int out_blocks  = (NNODES * (DIM / 4) + 255) / 256;
    const int w_blocks    = (NOUT * (DIM / 4) + 255) / 256;
    dim3 gg(NOUT / BN, NROWS_PAD / BM);   // (6, 391)

    // ---- Layer 1: T = [x@W1l^T | x@W1r^T] ----
    convert_x<<<rows_blocks, 256>>>((const float4*)x, acat);
    convert_w<<<w_blocks, 256>>>((const float4*)W1l, (const float4*)W1r, wcat);
    gemm_mma2<<<gg, 256, SMEM_GEMM>>>(acat, wcat, T);
    zero_f4<<<2048, 256>>>((float4*)sum, n4);
    zero_f4<<<64, 256>>>((float4*)deg, NNODES / 4);
    scatter_deg<<<(NEDGES + 255) / 256, 256>>>(ei, deg);
    scatter_addT<<<NEDGES, 192>>>(T, ei, sum);
    combine_split<<<rows_blocks, 256>>>((const float4*)sum, deg, b1l, T, acat);

    // ---- Layer 2 ----
    convert_w<<<w_blocks, 256>>>((const float4*)W2l, (const float4*)W2r, wcat);
    gemm_mma2<<<gg, 256, SMEM_GEMM>>>(acat, wcat, T);
    zero_f4<<<2048, 256>>>((float4*)sum, n4);
    scatter_addT<<<NEDGES, 192>>>(T, ei, sum);
    combine_final<<<out_blocks, 256>>>((const float4*)sum, deg, b2l, T,
                                       (float4*)out);
}

// round 6
// speedup vs baseline: 3.7554x; 1.4353x over previous
#include <cuda_runtime.h>
#include <cuda_bf16.h>
#include <cstdint>

#define NNODES    50000
#define NROWS_PAD 50048
#define NEDGES    100000
#define DIM       768
#define NOUT      1536       // T cols: [x@Wl^T (768) | x@Wr^T (768)]

// ---- scratch (allocation-free rule: __device__ globals) -------------------
__device__ float g_sum[(size_t)NNODES * DIM];               // 153 MB
__device__ float g_deg[NNODES];
__device__ float g_T[(size_t)NROWS_PAD * NOUT];             // 307 MB
__device__ float g_A[(size_t)NROWS_PAD * DIM];              // 154 MB (tf32-rounded)
__device__ float g_W[(size_t)NOUT * DIM];                   // 4.7 MB (tf32-rounded)

// ---------------------------------------------------------------------------
__device__ __forceinline__ uint32_t smem_u32(const void* p) {
    uint32_t a;
    asm("{ .reg .u64 t; cvta.to.shared.u64 t, %1; cvt.u32.u64 %0, t; }"
        : "=r"(a) : "l"(p));
    return a;
}
__device__ __forceinline__ float to_tf32(float f) {
    uint32_t u;
    asm("cvt.rna.tf32.f32 %0, %1;" : "=r"(u) : "f"(f));
    return __uint_as_float(u);
}

// ---------------------------------------------------------------------------
// Aggregation kernels
// ---------------------------------------------------------------------------
__global__ void zero_f4(float4* __restrict__ p, int n4) {
    int i = blockIdx.x * blockDim.x + threadIdx.x;
    int stride = gridDim.x * blockDim.x;
    float4 z = make_float4(0.f, 0.f, 0.f, 0.f);
    for (; i < n4; i += stride) p[i] = z;
}
__global__ void scatter_deg(const int* __restrict__ ei, float* __restrict__ deg) {
    int e = blockIdx.x * blockDim.x + threadIdx.x;
    if (e < NEDGES) atomicAdd(&deg[ei[NEDGES + e]], 1.0f);
}
// gather src row of T's left half (row stride NOUT), vector-reduce into sum
__global__ void __launch_bounds__(192) scatter_addT(
    const float* __restrict__ T, const int* __restrict__ ei,
    float* __restrict__ sum)
{
    int e = blockIdx.x;
    int s = ei[e];
    int d = ei[NEDGES + e];
    float4 v = ((const float4*)(T + (size_t)s * NOUT))[threadIdx.x];
    float* out = sum + (size_t)d * DIM + threadIdx.x * 4;
    asm volatile("red.global.add.v4.f32 [%0], {%1,%2,%3,%4};"
                 :: "l"(out), "f"(v.x), "f"(v.y), "f"(v.z), "f"(v.w) : "memory");
}

// ---------------------------------------------------------------------------
// tf32-rounding prep kernels
// ---------------------------------------------------------------------------
__global__ void convert_x(const float4* __restrict__ x, float4* __restrict__ A) {
    const int F4 = DIM / 4;
    int i = blockIdx.x * blockDim.x + threadIdx.x;
    if (i >= NROWS_PAD * F4) return;
    int r = i / F4;
    float4 v = make_float4(0.f, 0.f, 0.f, 0.f);
    if (r < NNODES) {
        v = x[i];
        v.x = to_tf32(v.x); v.y = to_tf32(v.y);
        v.z = to_tf32(v.z); v.w = to_tf32(v.w);
    }
    A[i] = v;
}

// W rows 0..767 = Wl, 768..1535 = Wr, tf32-rounded
__global__ void convert_w(const float4* __restrict__ Wl, const float4* __restrict__ Wr,
                          float4* __restrict__ W)
{
    const int F4 = DIM / 4;
    int i = blockIdx.x * blockDim.x + threadIdx.x;
    if (i >= NOUT * F4) return;
    float4 v = (i < DIM * F4) ? Wl[i] : Wr[i - DIM * F4];
    v.x = to_tf32(v.x); v.y = to_tf32(v.y);
    v.z = to_tf32(v.z); v.w = to_tf32(v.w);
    W[i] = v;
}

// layer-1 combine: h = relu(sum/deg + b + T_r), tf32-rounded into A
__global__ void combine_relu(const float4* __restrict__ sum, const float* __restrict__ deg,
                             const float* __restrict__ bias, const float* __restrict__ T,
                             float4* __restrict__ A)
{
    const int F4 = DIM / 4;
    int i = blockIdx.x * blockDim.x + threadIdx.x;
    if (i >= NROWS_PAD * F4) return;
    int r = i / F4, c = (i % F4) * 4;
    float4 v = make_float4(0.f, 0.f, 0.f, 0.f);
    if (r < NNODES) {
        float inv = 1.0f / fmaxf(deg[r], 1.0f);
        float4 s = sum[i];
        float4 t = *(const float4*)(T + (size_t)r * NOUT + DIM + c);
        v.x = to_tf32(fmaxf(s.x * inv + bias[c + 0] + t.x, 0.f));
        v.y = to_tf32(fmaxf(s.y * inv + bias[c + 1] + t.y, 0.f));
        v.z = to_tf32(fmaxf(s.z * inv + bias[c + 2] + t.z, 0.f));
        v.w = to_tf32(fmaxf(s.w * inv + bias[c + 3] + t.w, 0.f));
    }
    A[i] = v;
}

// layer-2 combine: out = sum/deg + b + T_r
__global__ void combine_final(const float4* __restrict__ sum, const float* __restrict__ deg,
                              const float* __restrict__ bias, const float* __restrict__ T,
                              float4* __restrict__ out)
{
    const int F4 = DIM / 4;
    int i = blockIdx.x * blockDim.x + threadIdx.x;
    if (i >= NNODES * F4) return;
    int r = i / F4, c = (i % F4) * 4;
    float inv = 1.0f / fmaxf(deg[r], 1.0f);
    float4 s = sum[i];
    float4 t = *(const float4*)(T + (size_t)r * NOUT + DIM + c);
    float4 v;
    v.x = s.x * inv + bias[c + 0] + t.x;
    v.y = s.y * inv + bias[c + 1] + t.y;
    v.z = s.z * inv + bias[c + 2] + t.z;
    v.w = s.w * inv + bias[c + 3] + t.w;
    out[i] = v;
}

// ---------------------------------------------------------------------------
// tf32 mma.sync GEMM: T[128m x 256n] = A @ W^T (K=768)
// BM=128 BN=256 BK=32 (128B rows), 8 warps (2m x 4n), warp tile 64x64,
// 4-slot cp.async pipeline, ldmatrix.x4.b16 emulating tf32 fragment loads.
// ---------------------------------------------------------------------------
#define BM 128
#define BN 256
#define ROW_B 128                   // bytes per smem row (32 tf32)
#define ATILE_B (BM * ROW_B)        // 16 KB
#define BTILE_B (BN * ROW_B)        // 32 KB
#define STG_B   (ATILE_B + BTILE_B) // 48 KB
#define SMEM_GEMM (4 * STG_B)       // 192 KB
#define NCH 24                      // 768 / 32
#define AROW_BYTES (DIM * 4)        // 3072

__device__ __forceinline__ void cp_async16(uint32_t saddr, const void* gaddr) {
    asm volatile("cp.async.cg.shared.global [%0], [%1], 16;"
                 :: "r"(saddr), "l"(gaddr));
}
__device__ __forceinline__ void cp_commit() {
    asm volatile("cp.async.commit_group;" ::: "memory");
}
__device__ __forceinline__ void cp_wait2() {
    asm volatile("cp.async.wait_group 2;" ::: "memory");
}
__device__ __forceinline__ void ldmatrix4(uint32_t* a, uint32_t addr) {
    asm volatile("ldmatrix.sync.aligned.m8n8.x4.shared.b16 {%0,%1,%2,%3}, [%4];"
                 : "=r"(a[0]), "=r"(a[1]), "=r"(a[2]), "=r"(a[3]) : "r"(addr));
}
__device__ __forceinline__ void mma_tf32(float* c, const uint32_t* a, const uint32_t* b) {
    asm volatile(
        "mma.sync.aligned.m16n8k8.row.col.f32.tf32.tf32.f32 "
        "{%0,%1,%2,%3}, {%4,%5,%6,%7}, {%8,%9}, {%0,%1,%2,%3};"
        : "+f"(c[0]), "+f"(c[1]), "+f"(c[2]), "+f"(c[3])
        : "r"(a[0]), "r"(a[1]), "r"(a[2]), "r"(a[3]), "r"(b[0]), "r"(b[1]));
}

__device__ __forceinline__ void load_stage(
    uint32_t slot_base, const char* Ab, const char* Bb, size_t goff, int tid)
{
    const int j  = tid & 7;        // 16B chunk in 128B row
    const int r0 = tid >> 3;       // 0..31
    const size_t gj = goff + (size_t)j * 16;
#pragma unroll
    for (int s = 0; s < 4; ++s) {
        int row = r0 + s * 32;
        uint32_t soff = row * ROW_B + ((j ^ (row & 7)) << 4);
        cp_async16(slot_base + soff, Ab + (size_t)row * AROW_BYTES + gj);
    }
#pragma unroll
    for (int s = 0; s < 8; ++s) {
        int row = r0 + s * 32;
        uint32_t soff = row * ROW_B + ((j ^ (row & 7)) << 4);
        cp_async16(slot_base + ATILE_B + soff, Bb + (size_t)row * AROW_BYTES + gj);
    }
}

__global__ void __launch_bounds__(256, 1) gemm_tf32(
    const float* __restrict__ A, const float* __restrict__ W,
    float* __restrict__ T)
{
    extern __shared__ char smem[];
    const uint32_t sb = smem_u32(smem);
    const int tid = threadIdx.x;
    const int wid = tid >> 5, lid = tid & 31;
    const int wm = (wid & 1) * 64;
    const int wn = (wid >> 1) * 64;
    const int n0 = blockIdx.x * BN;       // x fastest: 6 CTAs share A tile via L2
    const int m0 = blockIdx.y * BM;

    const char* Ab = (const char*)A + (size_t)m0 * AROW_BYTES;
    const char* Bb = (const char*)W + (size_t)n0 * AROW_BYTES;

    float acc[4][8][4];
#pragma unroll
    for (int i = 0; i < 4; i++)
#pragma unroll
        for (int j = 0; j < 8; j++)
#pragma unroll
            for (int k = 0; k < 4; k++) acc[i][j][k] = 0.f;

#pragma unroll
    for (int p = 0; p < 3; ++p) {
        load_stage(sb + p * STG_B, Ab, Bb, (size_t)p * 128, tid);
        cp_commit();
    }

    // lane-constant addressing for tf32 ldmatrix fragment emulation
    //   A (m-tile mt): matrices {m0-7@c, m8-15@c, m0-7@c+1, m8-15@c+1}
    //   lane -> row = wm+mt*16 + (lid&7) + 8*((lid>>3)&1), chunk + (lid>>4)
    uint32_t rowoffA[4], swzA[4];
    const uint32_t hiA = lid >> 4;
#pragma unroll
    for (int mt = 0; mt < 4; ++mt) {
        int r = wm + mt * 16 + (lid & 7) + ((lid >> 3) & 1) * 8;
        rowoffA[mt] = r * ROW_B;
        swzA[mt] = r & 7;
    }
    //   B (n-pair bt): matrices {n0-7@c, n0-7@c+1, n8-15@c, n8-15@c+1}
    //   lane -> row = wn+bt*16 + (lid&7) + 8*(lid>>4), chunk + ((lid>>3)&1)
    uint32_t rowoffB[4], swzB[4];
    const uint32_t hiB = (lid >> 3) & 1;
#pragma unroll
    for (int bt = 0; bt < 4; ++bt) {
        int r = wn + bt * 16 + (lid & 7) + (lid >> 4) * 8;
        rowoffB[bt] = ATILE_B + r * ROW_B;
        swzB[bt] = r & 7;
    }

    for (int c = 0; c < NCH; ++c) {
        cp_wait2();
        __syncthreads();   // stage c visible; slot (c+3)&3 drained (iter c-1)

        const int cn = c + 3;
        if (cn < NCH) load_stage(sb + (cn & 3) * STG_B, Ab, Bb,
                                 (size_t)cn * 128, tid);
        cp_commit();

        const uint32_t sS = sb + (c & 3) * STG_B;
#pragma unroll
        for (int ks = 0; ks < 4; ++ks) {
            uint32_t bfrag[8][2];
#pragma unroll
            for (int bt = 0; bt < 4; ++bt) {
                uint32_t r[4];
                ldmatrix4(r, sS + rowoffB[bt] +
                             (((ks * 2 + hiB) ^ swzB[bt]) << 4));
                bfrag[bt * 2 + 0][0] = r[0]; bfrag[bt * 2 + 0][1] = r[1];
                bfrag[bt * 2 + 1][0] = r[2]; bfrag[bt * 2 + 1][1] = r[3];
            }
#pragma unroll
            for (int mt = 0; mt < 4; ++mt) {
                uint32_t afrag[4];
                ldmatrix4(afrag, sS + rowoffA[mt] +
                                 (((ks * 2 + hiA) ^ swzA[mt]) << 4));
#pragma unroll
                for (int nt = 0; nt < 8; ++nt)
                    mma_tf32(acc[mt][nt], afrag, bfrag[nt]);
            }
        }
    }

    // epilogue: raw fp32 store to T
#pragma unroll
    for (int mt = 0; mt < 4; ++mt) {
        int row_lo = m0 + wm + mt * 16 + (lid >> 2);
#pragma unroll
        for (int h = 0; h < 2; ++h) {
            int row = row_lo + h * 8;
            float* orow = T + (size_t)row * NOUT;
#pragma unroll
            for (int nt = 0; nt < 8; ++nt) {
                int col = n0 + wn + nt * 8 + (lid & 3) * 2;
                float2 v;
                v.x = acc[mt][nt][h * 2 + 0];
                v.y = acc[mt][nt][h * 2 + 1];
                *(float2*)(orow + col) = v;
            }
        }
    }
}

// ---------------------------------------------------------------------------
extern "C" void kernel_launch(void* const* d_in, const int* in_sizes, int n_in,
                              void* d_out, int out_size)
{
    const float* x   = (const float*)d_in[0];
    const int*   ei  = (const int*)d_in[1];     // int32 (JAX x64 disabled)
    const float* W1l = (const float*)d_in[2];
    const float* b1l = (const float*)d_in[3];
    const float* W1r = (const float*)d_in[4];
    const float* W2l = (const float*)d_in[5];
    const float* b2l = (const float*)d_in[6];
    const float* W2r = (const float*)d_in[7];
    float*       out = (float*)d_out;

    float *sum, *deg, *T, *A, *W;
    cudaGetSymbolAddress((void**)&sum, g_sum);
    cudaGetSymbolAddress((void**)&deg, g_deg);
    cudaGetSymbolAddress((void**)&T,   g_T);
    cudaGetSymbolAddress((void**)&A,   g_A);
    cudaGetSymbolAddress((void**)&W,   g_W);

    cudaFuncSetAttribute(gemm_tf32, cudaFuncAttributeMaxDynamicSharedMemorySize,
                         SMEM_GEMM);

    const int n4 = NNODES * (DIM / 4);
    const int rows_blocks = (NROWS_PAD * (DIM / 4) + 255) / 256;
    const int out_blocks  = (NNODES * (DIM / 4) + 255) / 256;
    const int w_blocks    = (NOUT * (DIM / 4) + 255) / 256;
    dim3 gg(NOUT / BN, NROWS_PAD / BM);   // (6, 391)

    // ---- Layer 1: T = [x@W1l^T | x@W1r^T] ----
    convert_x<<<rows_blocks, 256>>>((const float4*)x, (float4*)A);
    convert_w<<<w_blocks, 256>>>((const float4*)W1l, (const float4*)W1r, (float4*)W);
    gemm_tf32<<<gg, 256, SMEM_GEMM>>>(A, W, T);
    zero_f4<<<2048, 256>>>((float4*)sum, n4);
    zero_f4<<<64, 256>>>((float4*)deg, NNODES / 4);
    scatter_deg<<<(NEDGES + 255) / 256, 256>>>(ei, deg);
    scatter_addT<<<NEDGES, 192>>>(T, ei, sum);
    combine_relu<<<rows_blocks, 256>>>((const float4*)sum, deg, b1l, T, (float4*)A);

    // ---- Layer 2 ----
    convert_w<<<w_blocks, 256>>>((const float4*)W2l, (const float4*)W2r, (float4*)W);
    gemm_tf32<<<gg, 256, SMEM_GEMM>>>(A, W, T);
    zero_f4<<<2048, 256>>>((float4*)sum, n4);
    scatter_addT<<<NEDGES, 192>>>(T, ei, sum);
    combine_final<<<out_blocks, 256>>>((const float4*)sum, deg, b2l, T,
                                       (float4*)out);
}

// round 7
// speedup vs baseline: 4.0754x; 1.0852x over previous
#include <cuda_runtime.h>
#include <cstdint>

#define NNODES    50000
#define NROWS_PAD 50048
#define NEDGES    100000
#define DIM       768
#define NOUT      1536       // T cols: [x@Wl^T (768) | x@Wr^T (768)]

// ---- scratch (allocation-free rule: __device__ globals) -------------------
__device__ float g_T[(size_t)NROWS_PAD * NOUT];             // 307 MB
__device__ float g_A[(size_t)NROWS_PAD * DIM];              // 154 MB (tf32-rounded)
__device__ float g_W[(size_t)NOUT * DIM];                   // 4.7 MB (tf32-rounded)
__device__ int   g_cnt[NNODES];
__device__ int   g_off[NNODES + 1];
__device__ int   g_cur[NNODES];
__device__ int   g_csr_src[NEDGES];

// ---------------------------------------------------------------------------
__device__ __forceinline__ uint32_t smem_u32(const void* p) {
    uint32_t a;
    asm("{ .reg .u64 t; cvta.to.shared.u64 t, %1; cvt.u32.u64 %0, t; }"
        : "=r"(a) : "l"(p));
    return a;
}
__device__ __forceinline__ float to_tf32(float f) {
    uint32_t u;
    asm("cvt.rna.tf32.f32 %0, %1;" : "=r"(u) : "f"(f));
    return __uint_as_float(u);
}

// ---------------------------------------------------------------------------
// CSR build
// ---------------------------------------------------------------------------
__global__ void zero_int(int* __restrict__ p, int n) {
    int i = blockIdx.x * blockDim.x + threadIdx.x;
    if (i < n) p[i] = 0;
}
__global__ void count_deg(const int* __restrict__ ei, int* __restrict__ cnt) {
    int e = blockIdx.x * blockDim.x + threadIdx.x;
    if (e < NEDGES) atomicAdd(&cnt[ei[NEDGES + e]], 1);
}
// single-block exclusive scan over NNODES counts -> off, cur
__global__ void __launch_bounds__(1024) exscan(
    const int* __restrict__ cnt, int* __restrict__ off, int* __restrict__ cur)
{
    __shared__ int s[1024];
    __shared__ int carry;
    if (threadIdx.x == 0) carry = 0;
    __syncthreads();
    for (int base = 0; base < NNODES; base += 1024) {
        int i = base + threadIdx.x;
        int v = (i < NNODES) ? cnt[i] : 0;
        s[threadIdx.x] = v;
        __syncthreads();
#pragma unroll
        for (int ofs = 1; ofs < 1024; ofs <<= 1) {
            int t = (threadIdx.x >= ofs) ? s[threadIdx.x - ofs] : 0;
            __syncthreads();
            s[threadIdx.x] += t;
            __syncthreads();
        }
        int excl = s[threadIdx.x] - v + carry;
        if (i < NNODES) { off[i] = excl; cur[i] = excl; }
        __syncthreads();
        if (threadIdx.x == 1023) carry += s[1023];
        __syncthreads();
    }
    if (threadIdx.x == 0) off[NNODES] = carry;
}
__global__ void fill_csr(const int* __restrict__ ei, int* __restrict__ cur,
                         int* __restrict__ csr_src)
{
    int e = blockIdx.x * blockDim.x + threadIdx.x;
    if (e < NEDGES) {
        int pos = atomicAdd(&cur[ei[NEDGES + e]], 1);
        csr_src[pos] = ei[e];
    }
}

// ---------------------------------------------------------------------------
// tf32-rounding prep kernels
// ---------------------------------------------------------------------------
__global__ void convert_x(const float4* __restrict__ x, float4* __restrict__ A) {
    const int F4 = DIM / 4;
    int i = blockIdx.x * blockDim.x + threadIdx.x;
    if (i >= NROWS_PAD * F4) return;
    int r = i / F4;
    float4 v = make_float4(0.f, 0.f, 0.f, 0.f);
    if (r < NNODES) {
        v = x[i];
        v.x = to_tf32(v.x); v.y = to_tf32(v.y);
        v.z = to_tf32(v.z); v.w = to_tf32(v.w);
    }
    A[i] = v;
}
__global__ void convert_w(const float4* __restrict__ Wl, const float4* __restrict__ Wr,
                          float4* __restrict__ W)
{
    const int F4 = DIM / 4;
    int i = blockIdx.x * blockDim.x + threadIdx.x;
    if (i >= NOUT * F4) return;
    float4 v = (i < DIM * F4) ? Wl[i] : Wr[i - DIM * F4];
    v.x = to_tf32(v.x); v.y = to_tf32(v.y);
    v.z = to_tf32(v.z); v.w = to_tf32(v.w);
    W[i] = v;
}

// ---------------------------------------------------------------------------
// Fused CSR aggregation + normalize + bias + residual (+relu/tf32) per node.
// 192 threads/block, one block per dst node; thread t owns float4 at col 4t.
// ---------------------------------------------------------------------------
__global__ void __launch_bounds__(192) agg_combine(
    const float* __restrict__ T, const int* __restrict__ off,
    const int* __restrict__ csr_src, const float* __restrict__ bias,
    float* __restrict__ dst, int do_relu_round)
{
    const int d = blockIdx.x;
    const int t4 = threadIdx.x * 4;
    const int beg = off[d], end = off[d + 1];

    float4 acc = make_float4(0.f, 0.f, 0.f, 0.f);
    for (int i = beg; i < end; ++i) {
        int s = csr_src[i];
        float4 v = *(const float4*)(T + (size_t)s * NOUT + t4);
        acc.x += v.x; acc.y += v.y; acc.z += v.z; acc.w += v.w;
    }
    float inv = 1.0f / (float)max(end - beg, 1);
    float4 t = *(const float4*)(T + (size_t)d * NOUT + DIM + t4);
    float4 b = *(const float4*)(bias + t4);
    float4 v;
    v.x = acc.x * inv + b.x + t.x;
    v.y = acc.y * inv + b.y + t.y;
    v.z = acc.z * inv + b.z + t.z;
    v.w = acc.w * inv + b.w + t.w;
    if (do_relu_round) {
        v.x = to_tf32(fmaxf(v.x, 0.f)); v.y = to_tf32(fmaxf(v.y, 0.f));
        v.z = to_tf32(fmaxf(v.z, 0.f)); v.w = to_tf32(fmaxf(v.w, 0.f));
    }
    *(float4*)(dst + (size_t)d * DIM + t4) = v;
}

// zero padding rows of A once (rows NNODES..NROWS_PAD-1)
__global__ void zero_pad_rows(float4* __restrict__ A) {
    const int F4 = DIM / 4;
    int i = blockIdx.x * blockDim.x + threadIdx.x;
    int total = (NROWS_PAD - NNODES) * F4;
    if (i < total) A[(size_t)NNODES * F4 + i] = make_float4(0.f, 0.f, 0.f, 0.f);
}

// ---------------------------------------------------------------------------
// tf32 mma.sync GEMM: T[128m x 256n] = A @ W^T (K=768)  (unchanged from R6)
// ---------------------------------------------------------------------------
#define BM 128
#define BN 256
#define ROW_B 128
#define ATILE_B (BM * ROW_B)
#define BTILE_B (BN * ROW_B)
#define STG_B   (ATILE_B + BTILE_B)
#define SMEM_GEMM (4 * STG_B)
#define NCH 24
#define AROW_BYTES (DIM * 4)

__device__ __forceinline__ void cp_async16(uint32_t saddr, const void* gaddr) {
    asm volatile("cp.async.cg.shared.global [%0], [%1], 16;"
                 :: "r"(saddr), "l"(gaddr));
}
__device__ __forceinline__ void cp_commit() {
    asm volatile("cp.async.commit_group;" ::: "memory");
}
__device__ __forceinline__ void cp_wait2() {
    asm volatile("cp.async.wait_group 2;" ::: "memory");
}
__device__ __forceinline__ void ldmatrix4(uint32_t* a, uint32_t addr) {
    asm volatile("ldmatrix.sync.aligned.m8n8.x4.shared.b16 {%0,%1,%2,%3}, [%4];"
                 : "=r"(a[0]), "=r"(a[1]), "=r"(a[2]), "=r"(a[3]) : "r"(addr));
}
__device__ __forceinline__ void mma_tf32(float* c, const uint32_t* a, const uint32_t* b) {
    asm volatile(
        "mma.sync.aligned.m16n8k8.row.col.f32.tf32.tf32.f32 "
        "{%0,%1,%2,%3}, {%4,%5,%6,%7}, {%8,%9}, {%0,%1,%2,%3};"
        : "+f"(c[0]), "+f"(c[1]), "+f"(c[2]), "+f"(c[3])
        : "r"(a[0]), "r"(a[1]), "r"(a[2]), "r"(a[3]), "r"(b[0]), "r"(b[1]));
}

__device__ __forceinline__ void load_stage(
    uint32_t slot_base, const char* Ab, const char* Bb, size_t goff, int tid)
{
    const int j  = tid & 7;
    const int r0 = tid >> 3;
    const size_t gj = goff + (size_t)j * 16;
#pragma unroll
    for (int s = 0; s < 4; ++s) {
        int row = r0 + s * 32;
        uint32_t soff = row * ROW_B + ((j ^ (row & 7)) << 4);
        cp_async16(slot_base + soff, Ab + (size_t)row * AROW_BYTES + gj);
    }
#pragma unroll
    for (int s = 0; s < 8; ++s) {
        int row = r0 + s * 32;
        uint32_t soff = row * ROW_B + ((j ^ (row & 7)) << 4);
        cp_async16(slot_base + ATILE_B + soff, Bb + (size_t)row * AROW_BYTES + gj);
    }
}

__global__ void __launch_bounds__(256, 1) gemm_tf32(
    const float* __restrict__ A, const float* __restrict__ W,
    float* __restrict__ T)
{
    extern __shared__ char smem[];
    const uint32_t sb = smem_u32(smem);
    const int tid = threadIdx.x;
    const int wid = tid >> 5, lid = tid & 31;
    const int wm = (wid & 1) * 64;
    const int wn = (wid >> 1) * 64;
    const int n0 = blockIdx.x * BN;
    const int m0 = blockIdx.y * BM;

    const char* Ab = (const char*)A + (size_t)m0 * AROW_BYTES;
    const char* Bb = (const char*)W + (size_t)n0 * AROW_BYTES;

    float acc[4][8][4];
#pragma unroll
    for (int i = 0; i < 4; i++)
#pragma unroll
        for (int j = 0; j < 8; j++)
#pragma unroll
            for (int k = 0; k < 4; k++) acc[i][j][k] = 0.f;

#pragma unroll
    for (int p = 0; p < 3; ++p) {
        load_stage(sb + p * STG_B, Ab, Bb, (size_t)p * 128, tid);
        cp_commit();
    }

    uint32_t rowoffA[4], swzA[4];
    const uint32_t hiA = lid >> 4;
#pragma unroll
    for (int mt = 0; mt < 4; ++mt) {
        int r = wm + mt * 16 + (lid & 7) + ((lid >> 3) & 1) * 8;
        rowoffA[mt] = r * ROW_B;
        swzA[mt] = r & 7;
    }
    uint32_t rowoffB[4], swzB[4];
    const uint32_t hiB = (lid >> 3) & 1;
#pragma unroll
    for (int bt = 0; bt < 4; ++bt) {
        int r = wn + bt * 16 + (lid & 7) + (lid >> 4) * 8;
        rowoffB[bt] = ATILE_B + r * ROW_B;
        swzB[bt] = r & 7;
    }

    for (int c = 0; c < NCH; ++c) {
        cp_wait2();
        __syncthreads();

        const int cn = c + 3;
        if (cn < NCH) load_stage(sb + (cn & 3) * STG_B, Ab, Bb,
                                 (size_t)cn * 128, tid);
        cp_commit();

        const uint32_t sS = sb + (c & 3) * STG_B;
#pragma unroll
        for (int ks = 0; ks < 4; ++ks) {
            uint32_t bfrag[8][2];
#pragma unroll
            for (int bt = 0; bt < 4; ++bt) {
                uint32_t r[4];
                ldmatrix4(r, sS + rowoffB[bt] +
                             (((ks * 2 + hiB) ^ swzB[bt]) << 4));
                bfrag[bt * 2 + 0][0] = r[0]; bfrag[bt * 2 + 0][1] = r[1];
                bfrag[bt * 2 + 1][0] = r[2]; bfrag[bt * 2 + 1][1] = r[3];
            }
#pragma unroll
            for (int mt = 0; mt < 4; ++mt) {
                uint32_t afrag[4];
                ldmatrix4(afrag, sS + rowoffA[mt] +
                                 (((ks * 2 + hiA) ^ swzA[mt]) << 4));
#pragma unroll
                for (int nt = 0; nt < 8; ++nt)
                    mma_tf32(acc[mt][nt], afrag, bfrag[nt]);
            }
        }
    }

#pragma unroll
    for (int mt = 0; mt < 4; ++mt) {
        int row_lo = m0 + wm + mt * 16 + (lid >> 2);
#pragma unroll
        for (int h = 0; h < 2; ++h) {
            int row = row_lo + h * 8;
            float* orow = T + (size_t)row * NOUT;
#pragma unroll
            for (int nt = 0; nt < 8; ++nt) {
                int col = n0 + wn + nt * 8 + (lid & 3) * 2;
                float2 v;
                v.x = acc[mt][nt][h * 2 + 0];
                v.y = acc[mt][nt][h * 2 + 1];
                *(float2*)(orow + col) = v;
            }
        }
    }
}

// ---------------------------------------------------------------------------
extern "C" void kernel_launch(void* const* d_in, const int* in_sizes, int n_in,
                              void* d_out, int out_size)
{
    const float* x   = (const float*)d_in[0];
    const int*   ei  = (const int*)d_in[1];     // int32 (JAX x64 disabled)
    const float* W1l = (const float*)d_in[2];
    const float* b1l = (const float*)d_in[3];
    const float* W1r = (const float*)d_in[4];
    const float* W2l = (const float*)d_in[5];
    const float* b2l = (const float*)d_in[6];
    const float* W2r = (const float*)d_in[7];
    float*       out = (float*)d_out;

    float *T, *A, *W;
    int *cnt, *off, *cur, *csr;
    cudaGetSymbolAddress((void**)&T,   g_T);
    cudaGetSymbolAddress((void**)&A,   g_A);
    cudaGetSymbolAddress((void**)&W,   g_W);
    cudaGetSymbolAddress((void**)&cnt, g_cnt);
    cudaGetSymbolAddress((void**)&off, g_off);
    cudaGetSymbolAddress((void**)&cur, g_cur);
    cudaGetSymbolAddress((void**)&csr, g_csr_src);

    cudaFuncSetAttribute(gemm_tf32, cudaFuncAttributeMaxDynamicSharedMemorySize,
                         SMEM_GEMM);

    const int rows_blocks = (NROWS_PAD * (DIM / 4) + 255) / 256;
    const int w_blocks    = (NOUT * (DIM / 4) + 255) / 256;
    const int eb          = (NEDGES + 255) / 256;
    dim3 gg(NOUT / BN, NROWS_PAD / BM);   // (6, 391)

    // ---- CSR build (once) + conversions ----
    zero_int<<<(NNODES + 255) / 256, 256>>>(cnt, NNODES);
    count_deg<<<eb, 256>>>(ei, cnt);
    exscan<<<1, 1024>>>(cnt, off, cur);
    fill_csr<<<eb, 256>>>(ei, cur, csr);
    convert_x<<<rows_blocks, 256>>>((const float4*)x, (float4*)A);
    convert_w<<<w_blocks, 256>>>((const float4*)W1l, (const float4*)W1r, (float4*)W);

    // ---- Layer 1 ----
    gemm_tf32<<<gg, 256, SMEM_GEMM>>>(A, W, T);
    agg_combine<<<NNODES, 192>>>(T, off, csr, b1l, A, 1);   // A = relu(...) tf32

    // ---- Layer 2 ----
    convert_w<<<w_blocks, 256>>>((const float4*)W2l, (const float4*)W2r, (float4*)W);
    gemm_tf32<<<gg, 256, SMEM_GEMM>>>(A, W, T);
    agg_combine<<<NNODES, 192>>>(T, off, csr, b2l, out, 0); // out = fp32
}